// round 1
// baseline (speedup 1.0000x reference)
#include <cuda_runtime.h>
#include <cstdint>

#define S_DIM 128
#define I_DIM 256
#define CM    256
#define CC    32
#define CZ    128
#define M1    8192   // I_DIM * CC

// Scratch (device globals: allocation-free per harness rules)
__device__ float g_Ap[S_DIM * M1];          // [s][(i,c)]  A/s, tf32-rounded
__device__ float g_Bp[S_DIM * M1];          // [s][(j,d)]  B,   tf32-rounded
__device__ float g_S[(size_t)M1 * M1];      // outer [(i,c)][(j,d)], tf32-rounded

// ---------------------------------------------------------------------------
// helpers
// ---------------------------------------------------------------------------
__device__ __forceinline__ unsigned f2tf32(float f) {
    unsigned r;
    asm("cvt.rna.tf32.f32 %0, %1;" : "=r"(r) : "f"(f));
    return r;
}
__device__ __forceinline__ float tf32r(float f) { return __uint_as_float(f2tf32(f)); }

__device__ __forceinline__ void cp16(void* s, const void* g) {
    unsigned sa = (unsigned)__cvta_generic_to_shared(s);
    asm volatile("cp.async.cg.shared.global [%0], [%1], 16;\n" :: "r"(sa), "l"(g));
}
__device__ __forceinline__ void cp_commit() { asm volatile("cp.async.commit_group;\n"); }
template<int N> __device__ __forceinline__ void cp_wait() {
    asm volatile("cp.async.wait_group %0;\n" :: "n"(N));
}

__device__ __forceinline__ void mma_tf32(float c[4],
                                         unsigned a0, unsigned a1, unsigned a2, unsigned a3,
                                         unsigned b0, unsigned b1) {
    asm volatile(
        "mma.sync.aligned.m16n8k8.row.col.f32.tf32.tf32.f32 "
        "{%0,%1,%2,%3}, {%4,%5,%6,%7}, {%8,%9}, {%0,%1,%2,%3};"
        : "+f"(c[0]), "+f"(c[1]), "+f"(c[2]), "+f"(c[3])
        : "r"(a0), "r"(a1), "r"(a2), "r"(a3), "r"(b0), "r"(b1));
}

// ---------------------------------------------------------------------------
// Kernel 1: LayerNorm + dual projection.
//   x[s][i][256] -> A = xn@wl + bl, B = xn@wr + br
//   writes g_Ap[s][(i*32+c)] = tf32(A/128),  g_Bp[s][(i*32+c)] = tf32(B)
// CTA: 32 rows (one s, 32 consecutive i), 128 threads.
// ---------------------------------------------------------------------------
__global__ __launch_bounds__(128) void k_lnproj(
    const float* __restrict__ x, const float* __restrict__ lnw, const float* __restrict__ lnb,
    const float* __restrict__ wl, const float* __restrict__ bl,
    const float* __restrict__ wr, const float* __restrict__ br)
{
    extern __shared__ float sm[];
    float* xn  = sm;                   // 32 * 260 (padded)
    float* Wc  = sm + 32 * 260;        // 256 * 64  (cols 0..31 = wl, 32..63 = wr)
    float* mus = Wc + 256 * 64;        // 32
    float* rss = mus + 32;             // 32

    const int tid = threadIdx.x;
    const int g0  = blockIdx.x * 32;   // first global row (s*256 + i)
    const int s   = g0 >> 8;
    const int i0  = g0 & 255;

    // stage x rows (coalesced float4)
    const float4* xsrc = (const float4*)(x + (size_t)g0 * CM);
    for (int v = tid; v < 2048; v += 128) {
        float4 t = xsrc[v];
        int r = v >> 6, k = (v & 63) << 2;
        float* p = &xn[r * 260 + k];
        p[0] = t.x; p[1] = t.y; p[2] = t.z; p[3] = t.w;
    }
    // stage W
    for (int v = tid; v < 2048; v += 128) {
        float4 t = ((const float4*)wl)[v];
        int k = v >> 3, c = (v & 7) << 2;
        float* p = &Wc[k * 64 + c];
        p[0] = t.x; p[1] = t.y; p[2] = t.z; p[3] = t.w;
    }
    for (int v = tid; v < 2048; v += 128) {
        float4 t = ((const float4*)wr)[v];
        int k = v >> 3, c = (v & 7) << 2;
        float* p = &Wc[k * 64 + 32 + c];
        p[0] = t.x; p[1] = t.y; p[2] = t.z; p[3] = t.w;
    }
    __syncthreads();

    // LN statistics: warp w handles rows w*8 .. w*8+7
    const int warp = tid >> 5, lane = tid & 31;
    for (int rr = 0; rr < 8; rr++) {
        int r = warp * 8 + rr;
        const float* row = &xn[r * 260];
        float s1 = 0.f, s2 = 0.f;
        #pragma unroll
        for (int e = 0; e < 8; e++) {
            float v = row[e * 32 + lane];
            s1 += v; s2 += v * v;
        }
        #pragma unroll
        for (int o = 16; o; o >>= 1) {
            s1 += __shfl_xor_sync(0xffffffffu, s1, o);
            s2 += __shfl_xor_sync(0xffffffffu, s2, o);
        }
        if (lane == 0) {
            float mu = s1 * (1.f / 256.f);
            float var = s2 * (1.f / 256.f) - mu * mu;
            mus[r] = mu;
            rss[r] = rsqrtf(var + 1e-5f);
        }
    }
    __syncthreads();

    // normalize in place
    for (int n = 0; n < 64; n++) {
        int v = n * 128 + tid;            // 0..8191
        int r = v >> 8, k = v & 255;
        xn[r * 260 + k] = (xn[r * 260 + k] - mus[r]) * rss[r] * lnw[k] + lnb[k];
    }
    __syncthreads();

    // projection: thread -> 4 rows x 4 cols
    const int rg = tid >> 4;              // 0..7
    const int cg = tid & 15;              // 0..15
    const int c0 = cg << 2;

    float acc[4][4];
    #pragma unroll
    for (int rr = 0; rr < 4; rr++)
        #pragma unroll
        for (int cc = 0; cc < 4; cc++) {
            int c = c0 + cc;
            acc[rr][cc] = (c < 32) ? bl[c] : br[c - 32];
        }

    const float* xr0 = &xn[(rg * 4 + 0) * 260];
    const float* xr1 = &xn[(rg * 4 + 1) * 260];
    const float* xr2 = &xn[(rg * 4 + 2) * 260];
    const float* xr3 = &xn[(rg * 4 + 3) * 260];

    #pragma unroll 4
    for (int k = 0; k < 256; k++) {
        float4 w4 = *(const float4*)&Wc[k * 64 + c0];
        float x0 = xr0[k], x1 = xr1[k], x2 = xr2[k], x3 = xr3[k];
        acc[0][0] += x0 * w4.x; acc[0][1] += x0 * w4.y; acc[0][2] += x0 * w4.z; acc[0][3] += x0 * w4.w;
        acc[1][0] += x1 * w4.x; acc[1][1] += x1 * w4.y; acc[1][2] += x1 * w4.z; acc[1][3] += x1 * w4.w;
        acc[2][0] += x2 * w4.x; acc[2][1] += x2 * w4.y; acc[2][2] += x2 * w4.z; acc[2][3] += x2 * w4.w;
        acc[3][0] += x3 * w4.x; acc[3][1] += x3 * w4.y; acc[3][2] += x3 * w4.z; acc[3][3] += x3 * w4.w;
    }

    #pragma unroll
    for (int rr = 0; rr < 4; rr++) {
        int i = i0 + rg * 4 + rr;
        #pragma unroll
        for (int cc = 0; cc < 4; cc++) {
            int c = c0 + cc;
            float v = acc[rr][cc];
            if (c < 32)
                g_Ap[s * M1 + i * 32 + c] = __uint_as_float(f2tf32(v * (1.f / 128.f)));
            else
                g_Bp[s * M1 + i * 32 + (c - 32)] = __uint_as_float(f2tf32(v));
        }
    }
}

// ---------------------------------------------------------------------------
// Kernel 2: outer GEMM  S[m][n] = sum_k Ap[k][m] * Bp[k][n]
//   M = N = 8192, K = 128. CTA tile 128x128, 8 warps (2x4), warp tile 64x32.
//   K chunked by 32, cp.async double-buffered.
// ---------------------------------------------------------------------------
__global__ __launch_bounds__(256) void k_outer()
{
    extern __shared__ float sm[];
    float* As = sm;            // 2 * 32*132
    float* Bs = sm + 8448;     // 2 * 32*132

    const int tid  = threadIdx.x;
    const int warp = tid >> 5, lane = tid & 31;
    const int g = lane >> 2, q = lane & 3;
    const int wm = (warp >> 2) * 64, wn = (warp & 3) * 32;
    const int m0 = blockIdx.x * 128, n0 = blockIdx.y * 128;

    float acc[4][4][4];
    #pragma unroll
    for (int a = 0; a < 4; a++)
        #pragma unroll
        for (int b = 0; b < 4; b++)
            #pragma unroll
            for (int c = 0; c < 4; c++) acc[a][b][c] = 0.f;

    auto issue = [&](int kc, int buf) {
        #pragma unroll
        for (int it = 0; it < 4; it++) {
            int v = tid + it * 256;
            int kk = v >> 5, m4 = (v & 31) << 2;
            cp16(&As[buf * 4224 + kk * 132 + m4], &g_Ap[(kc * 32 + kk) * M1 + m0 + m4]);
            cp16(&Bs[buf * 4224 + kk * 132 + m4], &g_Bp[(kc * 32 + kk) * M1 + n0 + m4]);
        }
        cp_commit();
    };

    issue(0, 0);
    int buf = 0;
    for (int kc = 0; kc < 4; kc++) {
        if (kc < 3) { issue(kc + 1, buf ^ 1); cp_wait<1>(); }
        else        { cp_wait<0>(); }
        __syncthreads();
        const float* A = &As[buf * 4224];
        const float* B = &Bs[buf * 4224];
        #pragma unroll
        for (int ks = 0; ks < 4; ks++) {
            int k0 = ks * 8;
            unsigned af[4][4], bf[4][2];
            #pragma unroll
            for (int mt = 0; mt < 4; mt++) {
                int m = wm + mt * 16 + g;
                af[mt][0] = __float_as_uint(A[(k0 + q) * 132 + m]);
                af[mt][1] = __float_as_uint(A[(k0 + q) * 132 + m + 8]);
                af[mt][2] = __float_as_uint(A[(k0 + q + 4) * 132 + m]);
                af[mt][3] = __float_as_uint(A[(k0 + q + 4) * 132 + m + 8]);
            }
            #pragma unroll
            for (int nt = 0; nt < 4; nt++) {
                int n = wn + nt * 8 + g;
                bf[nt][0] = __float_as_uint(B[(k0 + q) * 132 + n]);
                bf[nt][1] = __float_as_uint(B[(k0 + q + 4) * 132 + n]);
            }
            #pragma unroll
            for (int mt = 0; mt < 4; mt++)
                #pragma unroll
                for (int nt = 0; nt < 4; nt++)
                    mma_tf32(acc[mt][nt], af[mt][0], af[mt][1], af[mt][2], af[mt][3],
                             bf[nt][0], bf[nt][1]);
        }
        __syncthreads();
        buf ^= 1;
    }

    // epilogue: tf32-round and store (GEMM2 consumes these as mma operands)
    #pragma unroll
    for (int mt = 0; mt < 4; mt++) {
        int r0 = m0 + wm + mt * 16 + g;
        #pragma unroll
        for (int nt = 0; nt < 4; nt++) {
            int c = n0 + wn + nt * 8 + q * 2;
            float2 v0, v1;
            v0.x = tf32r(acc[mt][nt][0]); v0.y = tf32r(acc[mt][nt][1]);
            v1.x = tf32r(acc[mt][nt][2]); v1.y = tf32r(acc[mt][nt][3]);
            *(float2*)&g_S[(size_t)r0 * M1 + c]       = v0;
            *(float2*)&g_S[(size_t)(r0 + 8) * M1 + c] = v1;
        }
    }
}

// ---------------------------------------------------------------------------
// Kernel 3: out[i][j][z] = sum_{c,d} S[i*32+c][j*32+d] * wo[c*32+d][z] + bo[z]
//   CTA: one i, 128 j (jb selects half), all 128 z. K=1024 in 32 chunks of 32.
//   A-chunk for chunk c is a CONTIGUOUS 16KB segment of S row (i*32+c).
// ---------------------------------------------------------------------------
__global__ __launch_bounds__(256) void k_proj2(const float* __restrict__ wo,
                                               const float* __restrict__ bo,
                                               float* __restrict__ out)
{
    extern __shared__ float sm[];
    float* As = sm;             // 2 * 128*36
    float* Bs = sm + 9216;      // 2 * 32*132

    const int tid  = threadIdx.x;
    const int warp = tid >> 5, lane = tid & 31;
    const int g = lane >> 2, q = lane & 3;
    const int wm = (warp >> 2) * 64, wn = (warp & 3) * 32;
    const int jb = blockIdx.x, i = blockIdx.y;

    float acc[4][4][4];
    #pragma unroll
    for (int a = 0; a < 4; a++)
        #pragma unroll
        for (int b = 0; b < 4; b++)
            #pragma unroll
            for (int c = 0; c < 4; c++) acc[a][b][c] = 0.f;

    auto issue = [&](int c, int buf) {
        #pragma unroll
        for (int it = 0; it < 4; it++) {
            int v = tid + it * 256;
            int j = v >> 3, d4 = (v & 7) << 2;
            cp16(&As[buf * 4608 + j * 36 + d4],
                 &g_S[(size_t)(i * 32 + c) * M1 + jb * 4096 + (v << 2)]);
            int dk = v >> 5, z4 = (v & 31) << 2;
            cp16(&Bs[buf * 4224 + dk * 132 + z4], &wo[(c * 32 + dk) * 128 + z4]);
        }
        cp_commit();
    };

    issue(0, 0);
    int buf = 0;
    for (int c = 0; c < 32; c++) {
        if (c < 31) { issue(c + 1, buf ^ 1); cp_wait<1>(); }
        else        { cp_wait<0>(); }
        __syncthreads();
        const float* A = &As[buf * 4608];
        const float* B = &Bs[buf * 4224];
        #pragma unroll
        for (int ks = 0; ks < 4; ks++) {
            int k0 = ks * 8;
            unsigned af[4][4], bf[4][2];
            #pragma unroll
            for (int mt = 0; mt < 4; mt++) {
                int m = wm + mt * 16 + g;
                af[mt][0] = __float_as_uint(A[m * 36 + k0 + q]);
                af[mt][1] = __float_as_uint(A[(m + 8) * 36 + k0 + q]);
                af[mt][2] = __float_as_uint(A[m * 36 + k0 + q + 4]);
                af[mt][3] = __float_as_uint(A[(m + 8) * 36 + k0 + q + 4]);
            }
            #pragma unroll
            for (int nt = 0; nt < 4; nt++) {
                int n = wn + nt * 8 + g;
                bf[nt][0] = f2tf32(B[(k0 + q) * 132 + n]);
                bf[nt][1] = f2tf32(B[(k0 + q + 4) * 132 + n]);
            }
            #pragma unroll
            for (int mt = 0; mt < 4; mt++)
                #pragma unroll
                for (int nt = 0; nt < 4; nt++)
                    mma_tf32(acc[mt][nt], af[mt][0], af[mt][1], af[mt][2], af[mt][3],
                             bf[nt][0], bf[nt][1]);
        }
        __syncthreads();
        buf ^= 1;
    }

    // epilogue: add bias, store
    #pragma unroll
    for (int mt = 0; mt < 4; mt++) {
        int j = jb * 128 + wm + mt * 16 + g;
        #pragma unroll
        for (int nt = 0; nt < 4; nt++) {
            int z = wn + nt * 8 + q * 2;
            float b0 = __ldg(&bo[z]), b1 = __ldg(&bo[z + 1]);
            float2 v0, v1;
            v0.x = acc[mt][nt][0] + b0; v0.y = acc[mt][nt][1] + b1;
            v1.x = acc[mt][nt][2] + b0; v1.y = acc[mt][nt][3] + b1;
            *(float2*)&out[(size_t)(i * 256 + j) * 128 + z]     = v0;
            *(float2*)&out[(size_t)(i * 256 + j + 8) * 128 + z] = v1;
        }
    }
}

// ---------------------------------------------------------------------------
extern "C" void kernel_launch(void* const* d_in, const int* in_sizes, int n_in,
                              void* d_out, int out_size)
{
    const float* x   = (const float*)d_in[0];
    const float* lnw = (const float*)d_in[1];
    const float* lnb = (const float*)d_in[2];
    const float* wl  = (const float*)d_in[3];
    const float* bl  = (const float*)d_in[4];
    const float* wr  = (const float*)d_in[5];
    const float* br  = (const float*)d_in[6];
    const float* wo  = (const float*)d_in[7];
    const float* bo  = (const float*)d_in[8];

    const int SM1 = (32 * 260 + 256 * 64 + 64) * 4;   // 99072 B
    const int SM2 = 2 * 8448 * 4;                     // 67584 B
    const int SM3 = (9216 + 8448) * 4;                // 70656 B

    cudaFuncSetAttribute(k_lnproj, cudaFuncAttributeMaxDynamicSharedMemorySize, SM1);
    cudaFuncSetAttribute(k_outer,  cudaFuncAttributeMaxDynamicSharedMemorySize, SM2);
    cudaFuncSetAttribute(k_proj2,  cudaFuncAttributeMaxDynamicSharedMemorySize, SM3);

    k_lnproj<<<1024, 128, SM1>>>(x, lnw, lnb, wl, bl, wr, br);
    k_outer<<<dim3(64, 64), 256, SM2>>>();
    k_proj2<<<dim3(2, 256), 256, SM3>>>(wo, bo, (float*)d_out);
}

// round 2
// speedup vs baseline: 1.4162x; 1.4162x over previous
#include <cuda_runtime.h>
#include <cstdint>

#define S_DIM 128
#define I_DIM 256
#define CM    256
#define CC    32
#define CZ    128
#define M1    8192   // I_DIM * CC
#define NROWS 32768  // S_DIM * I_DIM

// Scratch (device globals: allocation-free per harness rules)
__device__ float g_Ap[S_DIM * M1];          // [s][(i,c)]  A/s, tf32-rounded
__device__ float g_Bp[S_DIM * M1];          // [s][(j,d)]  B,   tf32-rounded
__device__ float g_S[(size_t)M1 * M1];      // outer [(i,c)][(j,d)], tf32-rounded
__device__ float g_mu[NROWS];
__device__ float g_rs[NROWS];

// ---------------------------------------------------------------------------
// helpers
// ---------------------------------------------------------------------------
__device__ __forceinline__ unsigned f2tf32(float f) {
    unsigned r;
    asm("cvt.rna.tf32.f32 %0, %1;" : "=r"(r) : "f"(f));
    return r;
}
__device__ __forceinline__ float tf32r(float f) { return __uint_as_float(f2tf32(f)); }

__device__ __forceinline__ void cp16(void* s, const void* g) {
    unsigned sa = (unsigned)__cvta_generic_to_shared(s);
    asm volatile("cp.async.cg.shared.global [%0], [%1], 16;\n" :: "r"(sa), "l"(g));
}
__device__ __forceinline__ void cp_commit() { asm volatile("cp.async.commit_group;\n"); }
template<int N> __device__ __forceinline__ void cp_wait() {
    asm volatile("cp.async.wait_group %0;\n" :: "n"(N));
}

__device__ __forceinline__ void mma_tf32(float c[4],
                                         unsigned a0, unsigned a1, unsigned a2, unsigned a3,
                                         unsigned b0, unsigned b1) {
    asm volatile(
        "mma.sync.aligned.m16n8k8.row.col.f32.tf32.tf32.f32 "
        "{%0,%1,%2,%3}, {%4,%5,%6,%7}, {%8,%9}, {%0,%1,%2,%3};"
        : "+f"(c[0]), "+f"(c[1]), "+f"(c[2]), "+f"(c[3])
        : "r"(a0), "r"(a1), "r"(a2), "r"(a3), "r"(b0), "r"(b1));
}

// ---------------------------------------------------------------------------
// Kernel 0: LN statistics. One warp per row (256 floats).
// ---------------------------------------------------------------------------
__global__ __launch_bounds__(256) void k_stats(const float* __restrict__ x)
{
    const int tid  = threadIdx.x;
    const int row  = blockIdx.x * 8 + (tid >> 5);
    const int lane = tid & 31;
    const float4* p = (const float4*)(x + (size_t)row * CM);
    float4 u = p[lane], v = p[lane + 32];
    float s1 = u.x + u.y + u.z + u.w + v.x + v.y + v.z + v.w;
    float s2 = u.x*u.x + u.y*u.y + u.z*u.z + u.w*u.w
             + v.x*v.x + v.y*v.y + v.z*v.z + v.w*v.w;
    #pragma unroll
    for (int o = 16; o; o >>= 1) {
        s1 += __shfl_xor_sync(0xffffffffu, s1, o);
        s2 += __shfl_xor_sync(0xffffffffu, s2, o);
    }
    if (lane == 0) {
        float mu  = s1 * (1.f / 256.f);
        float var = s2 * (1.f / 256.f) - mu * mu;
        g_mu[row] = mu;
        g_rs[row] = rsqrtf(var + 1e-5f);
    }
}

// ---------------------------------------------------------------------------
// Kernel 1: LN + dual projection via tensor cores.
//   GEMM: [32768 rows x 256] @ [256 x 64]  (cols 0..31 = wl, 32..63 = wr)
//   LN applied at A-fragment build. 3-pass tf32 hi/lo split for fp32-grade
//   precision: ah*bh + al*bh + ah*bl.
//   CTA: 64 rows x 64 cols, 4 warps (warp tile 32x32), K chunked by 32.
// ---------------------------------------------------------------------------
__global__ __launch_bounds__(128) void k_proj(
    const float* __restrict__ x, const float* __restrict__ lnw, const float* __restrict__ lnb,
    const float* __restrict__ wl, const float* __restrict__ bl,
    const float* __restrict__ wr, const float* __restrict__ br)
{
    extern __shared__ float sm[];
    float* Wsm  = sm;                       // [256][72]
    float* xs   = Wsm + 256 * 72;           // 2 x [64][36]
    float* lnws = xs + 2 * 64 * 36;         // 256
    float* lnbs = lnws + 256;               // 256

    const int tid  = threadIdx.x;
    const int warp = tid >> 5, lane = tid & 31;
    const int g = lane >> 2, q = lane & 3;
    const int wm = (warp >> 1) * 32, wn = (warp & 1) * 32;
    const int m0 = blockIdx.x * 64;

    // stage combined W [k][64] padded to 72
    const float4* wl4 = (const float4*)wl;
    const float4* wr4 = (const float4*)wr;
    for (int v = tid; v < 2048; v += 128) {
        int k = v >> 3, c = (v & 7) << 2;
        *(float4*)&Wsm[k * 72 + c]      = wl4[v];
        *(float4*)&Wsm[k * 72 + 32 + c] = wr4[v];
    }
    for (int v = tid; v < 256; v += 128) { lnws[v] = lnw[v]; lnbs[v] = lnb[v]; }

    // per-thread LN stats for the rows this thread touches
    float mus[2][2], rss[2][2];
    #pragma unroll
    for (int mt = 0; mt < 2; mt++) {
        int r = m0 + wm + mt * 16 + g;
        mus[mt][0] = g_mu[r];     rss[mt][0] = g_rs[r];
        mus[mt][1] = g_mu[r + 8]; rss[mt][1] = g_rs[r + 8];
    }

    float acc[2][4][4];
    #pragma unroll
    for (int nt = 0; nt < 4; nt++) {
        int c = wn + nt * 8 + q * 2;
        float b0 = (c < 32) ? bl[c] : br[c - 32];
        float b1 = (c + 1 < 32) ? bl[c + 1] : br[c + 1 - 32];
        #pragma unroll
        for (int mt = 0; mt < 2; mt++) {
            acc[mt][nt][0] = b0; acc[mt][nt][1] = b1;
            acc[mt][nt][2] = b0; acc[mt][nt][3] = b1;
        }
    }

    auto issue = [&](int kc, int buf) {
        #pragma unroll
        for (int it = 0; it < 4; it++) {
            int v = tid + it * 128;              // 0..511
            int r = v >> 3, k4 = (v & 7) << 2;
            cp16(&xs[buf * 2304 + r * 36 + k4],
                 &x[(size_t)(m0 + r) * CM + kc * 32 + k4]);
        }
        cp_commit();
    };

    issue(0, 0);
    int buf = 0;
    for (int kc = 0; kc < 8; kc++) {
        if (kc < 7) { issue(kc + 1, buf ^ 1); cp_wait<1>(); }
        else        { cp_wait<0>(); }
        __syncthreads();
        const float* X = &xs[buf * 2304];
        #pragma unroll
        for (int ks = 0; ks < 4; ks++) {
            int kl0 = ks * 8 + q, kl1 = kl0 + 4;
            int kg0 = kc * 32 + kl0, kg1 = kc * 32 + kl1;
            float w0 = lnws[kg0], c0 = lnbs[kg0];
            float w1 = lnws[kg1], c1 = lnbs[kg1];

            unsigned ah[2][4], al[2][4];
            #pragma unroll
            for (int mt = 0; mt < 2; mt++) {
                int mb = wm + mt * 16 + g;
                float v00 = (X[mb * 36 + kl0]       - mus[mt][0]) * rss[mt][0] * w0 + c0;
                float v10 = (X[(mb + 8) * 36 + kl0] - mus[mt][1]) * rss[mt][1] * w0 + c0;
                float v01 = (X[mb * 36 + kl1]       - mus[mt][0]) * rss[mt][0] * w1 + c1;
                float v11 = (X[(mb + 8) * 36 + kl1] - mus[mt][1]) * rss[mt][1] * w1 + c1;
                ah[mt][0] = f2tf32(v00); al[mt][0] = f2tf32(v00 - __uint_as_float(ah[mt][0]));
                ah[mt][1] = f2tf32(v10); al[mt][1] = f2tf32(v10 - __uint_as_float(ah[mt][1]));
                ah[mt][2] = f2tf32(v01); al[mt][2] = f2tf32(v01 - __uint_as_float(ah[mt][2]));
                ah[mt][3] = f2tf32(v11); al[mt][3] = f2tf32(v11 - __uint_as_float(ah[mt][3]));
            }
            unsigned bh[4][2], blo[4][2];
            #pragma unroll
            for (int nt = 0; nt < 4; nt++) {
                int n = wn + nt * 8 + g;
                float r0 = Wsm[kg0 * 72 + n], r1 = Wsm[kg1 * 72 + n];
                bh[nt][0] = f2tf32(r0); blo[nt][0] = f2tf32(r0 - __uint_as_float(bh[nt][0]));
                bh[nt][1] = f2tf32(r1); blo[nt][1] = f2tf32(r1 - __uint_as_float(bh[nt][1]));
            }
            #pragma unroll
            for (int mt = 0; mt < 2; mt++)
                #pragma unroll
                for (int nt = 0; nt < 4; nt++) {
                    mma_tf32(acc[mt][nt], ah[mt][0], ah[mt][1], ah[mt][2], ah[mt][3],
                             bh[nt][0], bh[nt][1]);
                    mma_tf32(acc[mt][nt], al[mt][0], al[mt][1], al[mt][2], al[mt][3],
                             bh[nt][0], bh[nt][1]);
                    mma_tf32(acc[mt][nt], ah[mt][0], ah[mt][1], ah[mt][2], ah[mt][3],
                             blo[nt][0], blo[nt][1]);
                }
        }
        __syncthreads();
        buf ^= 1;
    }

    // epilogue: split columns into A (scaled 1/128) and B scratch, tf32-rounded
    #pragma unroll
    for (int mt = 0; mt < 2; mt++) {
        #pragma unroll
        for (int rr = 0; rr < 2; rr++) {
            int r = m0 + wm + mt * 16 + g + rr * 8;
            int s = r >> 8, i = r & 255;
            #pragma unroll
            for (int nt = 0; nt < 4; nt++) {
                int c = wn + nt * 8 + q * 2;
                float v0 = acc[mt][nt][rr * 2], v1 = acc[mt][nt][rr * 2 + 1];
                if (c < 32) {
                    float2 o; o.x = tf32r(v0 * (1.f / 128.f)); o.y = tf32r(v1 * (1.f / 128.f));
                    *(float2*)&g_Ap[s * M1 + i * 32 + c] = o;
                } else {
                    float2 o; o.x = tf32r(v0); o.y = tf32r(v1);
                    *(float2*)&g_Bp[s * M1 + i * 32 + (c - 32)] = o;
                }
            }
        }
    }
}

// ---------------------------------------------------------------------------
// Kernel 2: outer GEMM  S[m][n] = sum_k Ap[k][m] * Bp[k][n]
//   M = N = 8192, K = 128. CTA 128x128, 4 warps, warp tile 64x64.
//   K chunks of 32, 3-stage cp.async, conflict-free pad 136.
// ---------------------------------------------------------------------------
__global__ __launch_bounds__(128) void k_outer()
{
    extern __shared__ float sm[];
    float* As = sm;              // 3 x [32][136]
    float* Bs = sm + 3 * 4352;   // 3 x [32][136]

    const int tid  = threadIdx.x;
    const int warp = tid >> 5, lane = tid & 31;
    const int g = lane >> 2, q = lane & 3;
    const int wm = (warp >> 1) * 64, wn = (warp & 1) * 64;
    const int m0 = blockIdx.x * 128, n0 = blockIdx.y * 128;

    float acc[4][8][4];
    #pragma unroll
    for (int a = 0; a < 4; a++)
        #pragma unroll
        for (int b = 0; b < 8; b++)
            #pragma unroll
            for (int c = 0; c < 4; c++) acc[a][b][c] = 0.f;

    auto issue = [&](int kc, int st) {
        #pragma unroll
        for (int it = 0; it < 8; it++) {
            int v = tid + it * 128;                 // 0..1023
            int kk = v >> 5, m4 = (v & 31) << 2;
            cp16(&As[st * 4352 + kk * 136 + m4], &g_Ap[(kc * 32 + kk) * M1 + m0 + m4]);
            cp16(&Bs[st * 4352 + kk * 136 + m4], &g_Bp[(kc * 32 + kk) * M1 + n0 + m4]);
        }
        cp_commit();
    };

    issue(0, 0); issue(1, 1); issue(2, 2);
    for (int kc = 0; kc < 4; kc++) {
        int left = 3 - kc;
        if (left >= 2)      cp_wait<2>();
        else if (left == 1) cp_wait<1>();
        else                cp_wait<0>();
        __syncthreads();
        const float* A = &As[(kc % 3) * 4352];
        const float* B = &Bs[(kc % 3) * 4352];
        #pragma unroll
        for (int ks = 0; ks < 4; ks++) {
            int k0 = ks * 8;
            unsigned af[4][4], bf[8][2];
            #pragma unroll
            for (int mt = 0; mt < 4; mt++) {
                int m = wm + mt * 16 + g;
                af[mt][0] = __float_as_uint(A[(k0 + q) * 136 + m]);
                af[mt][1] = __float_as_uint(A[(k0 + q) * 136 + m + 8]);
                af[mt][2] = __float_as_uint(A[(k0 + q + 4) * 136 + m]);
                af[mt][3] = __float_as_uint(A[(k0 + q + 4) * 136 + m + 8]);
            }
            #pragma unroll
            for (int nt = 0; nt < 8; nt++) {
                int n = wn + nt * 8 + g;
                bf[nt][0] = __float_as_uint(B[(k0 + q) * 136 + n]);
                bf[nt][1] = __float_as_uint(B[(k0 + q + 4) * 136 + n]);
            }
            #pragma unroll
            for (int mt = 0; mt < 4; mt++)
                #pragma unroll
                for (int nt = 0; nt < 8; nt++)
                    mma_tf32(acc[mt][nt], af[mt][0], af[mt][1], af[mt][2], af[mt][3],
                             bf[nt][0], bf[nt][1]);
        }
        __syncthreads();
        if (kc + 3 < 4) issue(kc + 3, kc % 3);
    }

    #pragma unroll
    for (int mt = 0; mt < 4; mt++) {
        int r0 = m0 + wm + mt * 16 + g;
        #pragma unroll
        for (int nt = 0; nt < 8; nt++) {
            int c = n0 + wn + nt * 8 + q * 2;
            float2 v0, v1;
            v0.x = tf32r(acc[mt][nt][0]); v0.y = tf32r(acc[mt][nt][1]);
            v1.x = tf32r(acc[mt][nt][2]); v1.y = tf32r(acc[mt][nt][3]);
            *(float2*)&g_S[(size_t)r0 * M1 + c]       = v0;
            *(float2*)&g_S[(size_t)(r0 + 8) * M1 + c] = v1;
        }
    }
}

// ---------------------------------------------------------------------------
// Kernel 3: out[i][j][z] = sum_{c,d} S[i*32+c][j*32+d] * wo[c*32+d][z] + bo[z]
//   CTA: one i, 128 j, 128 z. K=1024 in 32 chunks of 32, 3-stage cp.async.
//   4 warps, warp tile 64x64.
// ---------------------------------------------------------------------------
__global__ __launch_bounds__(128) void k_proj2(const float* __restrict__ wo,
                                               const float* __restrict__ bo,
                                               float* __restrict__ out)
{
    extern __shared__ float sm[];
    float* As = sm;               // 3 x [128][36]
    float* Bs = sm + 3 * 4608;    // 3 x [32][136]

    const int tid  = threadIdx.x;
    const int warp = tid >> 5, lane = tid & 31;
    const int g = lane >> 2, q = lane & 3;
    const int wm = (warp >> 1) * 64, wn = (warp & 1) * 64;
    const int jb = blockIdx.x, i = blockIdx.y;

    float acc[4][8][4];
    #pragma unroll
    for (int a = 0; a < 4; a++)
        #pragma unroll
        for (int b = 0; b < 8; b++)
            #pragma unroll
            for (int c = 0; c < 4; c++) acc[a][b][c] = 0.f;

    auto issue = [&](int c, int st) {
        #pragma unroll
        for (int it = 0; it < 8; it++) {
            int v = tid + it * 128;                 // 0..1023
            int j = v >> 3, d4 = (v & 7) << 2;
            cp16(&As[st * 4608 + j * 36 + d4],
                 &g_S[(size_t)(i * 32 + c) * M1 + jb * 4096 + (v << 2)]);
            int dk = v >> 5, z4 = (v & 31) << 2;
            cp16(&Bs[st * 4352 + dk * 136 + z4], &wo[(c * 32 + dk) * 128 + z4]);
        }
        cp_commit();
    };

    issue(0, 0); issue(1, 1); issue(2, 2);
    for (int c = 0; c < 32; c++) {
        int left = 31 - c;
        if (left >= 2)      cp_wait<2>();
        else if (left == 1) cp_wait<1>();
        else                cp_wait<0>();
        __syncthreads();
        const float* A = &As[(c % 3) * 4608];
        const float* B = &Bs[(c % 3) * 4352];
        #pragma unroll
        for (int ks = 0; ks < 4; ks++) {
            int k0 = ks * 8;
            unsigned af[4][4], bf[8][2];
            #pragma unroll
            for (int mt = 0; mt < 4; mt++) {
                int m = wm + mt * 16 + g;
                af[mt][0] = __float_as_uint(A[m * 36 + k0 + q]);
                af[mt][1] = __float_as_uint(A[(m + 8) * 36 + k0 + q]);
                af[mt][2] = __float_as_uint(A[m * 36 + k0 + q + 4]);
                af[mt][3] = __float_as_uint(A[(m + 8) * 36 + k0 + q + 4]);
            }
            #pragma unroll
            for (int nt = 0; nt < 8; nt++) {
                int n = wn + nt * 8 + g;
                bf[nt][0] = f2tf32(B[(k0 + q) * 136 + n]);
                bf[nt][1] = f2tf32(B[(k0 + q + 4) * 136 + n]);
            }
            #pragma unroll
            for (int mt = 0; mt < 4; mt++)
                #pragma unroll
                for (int nt = 0; nt < 8; nt++)
                    mma_tf32(acc[mt][nt], af[mt][0], af[mt][1], af[mt][2], af[mt][3],
                             bf[nt][0], bf[nt][1]);
        }
        __syncthreads();
        if (c + 3 < 32) issue(c + 3, c % 3);
    }

    #pragma unroll
    for (int mt = 0; mt < 4; mt++) {
        int j = jb * 128 + wm + mt * 16 + g;
        #pragma unroll
        for (int nt = 0; nt < 8; nt++) {
            int z = wn + nt * 8 + q * 2;
            float b0 = __ldg(&bo[z]), b1 = __ldg(&bo[z + 1]);
            float2 v0, v1;
            v0.x = acc[mt][nt][0] + b0; v0.y = acc[mt][nt][1] + b1;
            v1.x = acc[mt][nt][2] + b0; v1.y = acc[mt][nt][3] + b1;
            *(float2*)&out[(size_t)(i * 256 + j) * 128 + z]     = v0;
            *(float2*)&out[(size_t)(i * 256 + j + 8) * 128 + z] = v1;
        }
    }
}

// ---------------------------------------------------------------------------
extern "C" void kernel_launch(void* const* d_in, const int* in_sizes, int n_in,
                              void* d_out, int out_size)
{
    const float* x   = (const float*)d_in[0];
    const float* lnw = (const float*)d_in[1];
    const float* lnb = (const float*)d_in[2];
    const float* wl  = (const float*)d_in[3];
    const float* bl  = (const float*)d_in[4];
    const float* wr  = (const float*)d_in[5];
    const float* br  = (const float*)d_in[6];
    const float* wo  = (const float*)d_in[7];
    const float* bo  = (const float*)d_in[8];

    const int SMP = (256 * 72 + 2 * 64 * 36 + 512) * 4;        // 94720 B
    const int SM2 = 6 * 4352 * 4;                              // 104448 B
    const int SM3 = (3 * 4608 + 3 * 4352) * 4;                 // 107520 B

    cudaFuncSetAttribute(k_proj,  cudaFuncAttributeMaxDynamicSharedMemorySize, SMP);
    cudaFuncSetAttribute(k_outer, cudaFuncAttributeMaxDynamicSharedMemorySize, SM2);
    cudaFuncSetAttribute(k_proj2, cudaFuncAttributeMaxDynamicSharedMemorySize, SM3);

    k_stats<<<4096, 256>>>(x);
    k_proj<<<512, 128, SMP>>>(x, lnw, lnb, wl, bl, wr, br);
    k_outer<<<dim3(64, 64), 128, SM2>>>();
    k_proj2<<<dim3(2, 256), 128, SM3>>>(wo, bo, (float*)d_out);
}

// round 3
// speedup vs baseline: 1.9113x; 1.3496x over previous
#include <cuda_runtime.h>
#include <cuda_fp16.h>
#include <cstdint>

#define S_DIM 128
#define I_DIM 256
#define CM    256
#define CC    32
#define CZ    128
#define M1    8192   // I_DIM * CC
#define NROWS 32768  // S_DIM * I_DIM

// Scratch (device globals: allocation-free per harness rules)
__device__ __half g_Ah[(size_t)M1 * S_DIM];     // [(i,c)][s]  A/128, fp16
__device__ __half g_Bh[(size_t)M1 * S_DIM];     // [(j,d)][s]  B,     fp16
__device__ __half g_S16[(size_t)M1 * M1];       // outer [(i,c)][(j,d)], fp16
__device__ __half g_woT[CZ * 1024];             // [z][(c,d)] fp16 transposed w_out
__device__ float  g_mu[NROWS];
__device__ float  g_rs[NROWS];

// ---------------------------------------------------------------------------
// helpers
// ---------------------------------------------------------------------------
__device__ __forceinline__ unsigned f2tf32(float f) {
    unsigned r;
    asm("cvt.rna.tf32.f32 %0, %1;" : "=r"(r) : "f"(f));
    return r;
}

__device__ __forceinline__ void cp16(void* s, const void* g) {
    unsigned sa = (unsigned)__cvta_generic_to_shared(s);
    asm volatile("cp.async.cg.shared.global [%0], [%1], 16;\n" :: "r"(sa), "l"(g));
}
__device__ __forceinline__ void cp8(void* s, const void* g) {
    unsigned sa = (unsigned)__cvta_generic_to_shared(s);
    asm volatile("cp.async.ca.shared.global [%0], [%1], 8;\n" :: "r"(sa), "l"(g));
}
__device__ __forceinline__ void cp_commit() { asm volatile("cp.async.commit_group;\n"); }
template<int N> __device__ __forceinline__ void cp_wait() {
    asm volatile("cp.async.wait_group %0;\n" :: "n"(N));
}

__device__ __forceinline__ void mma_tf32(float c[4],
                                         unsigned a0, unsigned a1, unsigned a2, unsigned a3,
                                         unsigned b0, unsigned b1) {
    asm volatile(
        "mma.sync.aligned.m16n8k8.row.col.f32.tf32.tf32.f32 "
        "{%0,%1,%2,%3}, {%4,%5,%6,%7}, {%8,%9}, {%0,%1,%2,%3};"
        : "+f"(c[0]), "+f"(c[1]), "+f"(c[2]), "+f"(c[3])
        : "r"(a0), "r"(a1), "r"(a2), "r"(a3), "r"(b0), "r"(b1));
}

__device__ __forceinline__ void mma_f16(float c[4],
                                        unsigned a0, unsigned a1, unsigned a2, unsigned a3,
                                        unsigned b0, unsigned b1) {
    asm volatile(
        "mma.sync.aligned.m16n8k16.row.col.f32.f16.f16.f32 "
        "{%0,%1,%2,%3}, {%4,%5,%6,%7}, {%8,%9}, {%0,%1,%2,%3};"
        : "+f"(c[0]), "+f"(c[1]), "+f"(c[2]), "+f"(c[3])
        : "r"(a0), "r"(a1), "r"(a2), "r"(a3), "r"(b0), "r"(b1));
}

// ---------------------------------------------------------------------------
// Kernel 0: LN statistics. One warp per row (256 floats).
// ---------------------------------------------------------------------------
__global__ __launch_bounds__(256) void k_stats(const float* __restrict__ x)
{
    const int tid  = threadIdx.x;
    const int row  = blockIdx.x * 8 + (tid >> 5);
    const int lane = tid & 31;
    const float4* p = (const float4*)(x + (size_t)row * CM);
    float4 u = p[lane], v = p[lane + 32];
    float s1 = u.x + u.y + u.z + u.w + v.x + v.y + v.z + v.w;
    float s2 = u.x*u.x + u.y*u.y + u.z*u.z + u.w*u.w
             + v.x*v.x + v.y*v.y + v.z*v.z + v.w*v.w;
    #pragma unroll
    for (int o = 16; o; o >>= 1) {
        s1 += __shfl_xor_sync(0xffffffffu, s1, o);
        s2 += __shfl_xor_sync(0xffffffffu, s2, o);
    }
    if (lane == 0) {
        float mu  = s1 * (1.f / 256.f);
        float var = s2 * (1.f / 256.f) - mu * mu;
        g_mu[row] = mu;
        g_rs[row] = rsqrtf(var + 1e-5f);
    }
}

// ---------------------------------------------------------------------------
// Kernel 0b: transpose w_out -> g_woT[z][(c,d)] fp16
// ---------------------------------------------------------------------------
__global__ __launch_bounds__(256) void k_woT(const float* __restrict__ wo)
{
    const int z = blockIdx.x;
    for (int k = threadIdx.x; k < 1024; k += 256)
        g_woT[z * 1024 + k] = __float2half(wo[k * CZ + z]);
}

// ---------------------------------------------------------------------------
// Kernel 1: LN + dual projection via tensor cores (tf32 3-pass, fp32-grade).
//   Row mapping: r = i*128 + s  (CTA: fixed i, 64 consecutive s).
//   Epilogue: smem transpose, write fp16 g_Ah[(i,c)][s] (scaled 1/128) and
//   g_Bh[(i,d)][s].
// ---------------------------------------------------------------------------
__global__ __launch_bounds__(128) void k_proj(
    const float* __restrict__ x, const float* __restrict__ lnw, const float* __restrict__ lnb,
    const float* __restrict__ wl, const float* __restrict__ bl,
    const float* __restrict__ wr, const float* __restrict__ br)
{
    extern __shared__ float sm[];
    float* Wsm  = sm;                       // [256][72]
    float* xs   = Wsm + 256 * 72;           // 2 x [64][36]
    float* lnws = xs + 2 * 64 * 36;         // 256
    float* lnbs = lnws + 256;               // 256

    const int tid  = threadIdx.x;
    const int warp = tid >> 5, lane = tid & 31;
    const int g = lane >> 2, q = lane & 3;
    const int wm = (warp >> 1) * 32, wn = (warp & 1) * 32;
    const int m0 = blockIdx.x * 64;
    const int i  = m0 >> 7;           // fixed i for this CTA
    const int s0 = m0 & 127;          // 0 or 64

    // stage combined W [k][64] padded to 72
    const float4* wl4 = (const float4*)wl;
    const float4* wr4 = (const float4*)wr;
    for (int v = tid; v < 2048; v += 128) {
        int k = v >> 3, c = (v & 7) << 2;
        *(float4*)&Wsm[k * 72 + c]      = wl4[v];
        *(float4*)&Wsm[k * 72 + 32 + c] = wr4[v];
    }
    for (int v = tid; v < 256; v += 128) { lnws[v] = lnw[v]; lnbs[v] = lnb[v]; }

    // per-thread LN stats (x-row = s*256 + i)
    float mus[2][2], rss[2][2];
    #pragma unroll
    for (int mt = 0; mt < 2; mt++) {
        int s = s0 + wm + mt * 16 + g;
        mus[mt][0] = g_mu[s * 256 + i];       rss[mt][0] = g_rs[s * 256 + i];
        mus[mt][1] = g_mu[(s + 8) * 256 + i]; rss[mt][1] = g_rs[(s + 8) * 256 + i];
    }

    float acc[2][4][4];
    #pragma unroll
    for (int nt = 0; nt < 4; nt++) {
        int c = wn + nt * 8 + q * 2;
        float b0 = (c < 32) ? bl[c] : br[c - 32];
        float b1 = (c + 1 < 32) ? bl[c + 1] : br[c + 1 - 32];
        #pragma unroll
        for (int mt = 0; mt < 2; mt++) {
            acc[mt][nt][0] = b0; acc[mt][nt][1] = b1;
            acc[mt][nt][2] = b0; acc[mt][nt][3] = b1;
        }
    }

    auto issue = [&](int kc, int buf) {
        #pragma unroll
        for (int it = 0; it < 4; it++) {
            int v = tid + it * 128;              // 0..511
            int r = v >> 3, k4 = (v & 7) << 2;   // local row, k offset
            cp16(&xs[buf * 2304 + r * 36 + k4],
                 &x[(size_t)((s0 + r) * 256 + i) * CM + kc * 32 + k4]);
        }
        cp_commit();
    };

    issue(0, 0);
    int buf = 0;
    for (int kc = 0; kc < 8; kc++) {
        if (kc < 7) { issue(kc + 1, buf ^ 1); cp_wait<1>(); }
        else        { cp_wait<0>(); }
        __syncthreads();
        const float* X = &xs[buf * 2304];
        #pragma unroll
        for (int ks = 0; ks < 4; ks++) {
            int kl0 = ks * 8 + q, kl1 = kl0 + 4;
            int kg0 = kc * 32 + kl0, kg1 = kc * 32 + kl1;
            float w0 = lnws[kg0], c0 = lnbs[kg0];
            float w1 = lnws[kg1], c1 = lnbs[kg1];

            unsigned ah[2][4], al[2][4];
            #pragma unroll
            for (int mt = 0; mt < 2; mt++) {
                int mb = wm + mt * 16 + g;
                float v00 = (X[mb * 36 + kl0]       - mus[mt][0]) * rss[mt][0] * w0 + c0;
                float v10 = (X[(mb + 8) * 36 + kl0] - mus[mt][1]) * rss[mt][1] * w0 + c0;
                float v01 = (X[mb * 36 + kl1]       - mus[mt][0]) * rss[mt][0] * w1 + c1;
                float v11 = (X[(mb + 8) * 36 + kl1] - mus[mt][1]) * rss[mt][1] * w1 + c1;
                ah[mt][0] = f2tf32(v00); al[mt][0] = f2tf32(v00 - __uint_as_float(ah[mt][0]));
                ah[mt][1] = f2tf32(v10); al[mt][1] = f2tf32(v10 - __uint_as_float(ah[mt][1]));
                ah[mt][2] = f2tf32(v01); al[mt][2] = f2tf32(v01 - __uint_as_float(ah[mt][2]));
                ah[mt][3] = f2tf32(v11); al[mt][3] = f2tf32(v11 - __uint_as_float(ah[mt][3]));
            }
            unsigned bh[4][2], blo[4][2];
            #pragma unroll
            for (int nt = 0; nt < 4; nt++) {
                int n = wn + nt * 8 + g;
                float r0 = Wsm[kg0 * 72 + n], r1 = Wsm[kg1 * 72 + n];
                bh[nt][0] = f2tf32(r0); blo[nt][0] = f2tf32(r0 - __uint_as_float(bh[nt][0]));
                bh[nt][1] = f2tf32(r1); blo[nt][1] = f2tf32(r1 - __uint_as_float(bh[nt][1]));
            }
            #pragma unroll
            for (int mt = 0; mt < 2; mt++)
                #pragma unroll
                for (int nt = 0; nt < 4; nt++) {
                    mma_tf32(acc[mt][nt], ah[mt][0], ah[mt][1], ah[mt][2], ah[mt][3],
                             bh[nt][0], bh[nt][1]);
                    mma_tf32(acc[mt][nt], al[mt][0], al[mt][1], al[mt][2], al[mt][3],
                             bh[nt][0], bh[nt][1]);
                    mma_tf32(acc[mt][nt], ah[mt][0], ah[mt][1], ah[mt][2], ah[mt][3],
                             blo[nt][0], blo[nt][1]);
                }
        }
        __syncthreads();
        buf ^= 1;
    }

    // epilogue: transpose via smem (overlay on xs), write fp16 [m][s]
    __half* T = (__half*)xs;                 // [64 cols][72 s] half, 16B-aligned rows
    #pragma unroll
    for (int mt = 0; mt < 2; mt++) {
        #pragma unroll
        for (int rr = 0; rr < 2; rr++) {
            int lr = wm + mt * 16 + g + rr * 8;      // local s index 0..63
            #pragma unroll
            for (int nt = 0; nt < 4; nt++) {
                int col = wn + nt * 8 + q * 2;
                float v0 = acc[mt][nt][rr * 2], v1 = acc[mt][nt][rr * 2 + 1];
                if (col < 32) { v0 *= (1.f / 128.f); v1 *= (1.f / 128.f); }
                T[col * 72 + lr]       = __float2half(v0);
                T[(col + 1) * 72 + lr] = __float2half(v1);
            }
        }
    }
    __syncthreads();
    {
        int col = tid >> 1, sh = (tid & 1) * 32;
        const int4* src = (const int4*)&T[col * 72 + sh];
        __half* dst = (col < 32)
            ? &g_Ah[(size_t)(i * 32 + col) * S_DIM + s0 + sh]
            : &g_Bh[(size_t)(i * 32 + (col - 32)) * S_DIM + s0 + sh];
        int4* d4 = (int4*)dst;
        d4[0] = src[0]; d4[1] = src[1]; d4[2] = src[2]; d4[3] = src[3];
    }
}

// ---------------------------------------------------------------------------
// Kernel 2: outer GEMM (fp16)  S[m][n] = sum_s Ah[m][s] * Bh[n][s]
//   M = N = 8192, K = 128. CTA 128x128, 4 warps, warp tile 64x64.
//   K chunks of 32, 3-stage cp.async. smem rows: 32 halves + 8 pad = 40.
// ---------------------------------------------------------------------------
__global__ __launch_bounds__(128) void k_outer()
{
    extern __shared__ __half smh[];
    __half* As = smh;               // 3 x [128][40]
    __half* Bs = smh + 3 * 5120;    // 3 x [128][40]

    const int tid  = threadIdx.x;
    const int warp = tid >> 5, lane = tid & 31;
    const int g = lane >> 2, q = lane & 3;
    const int wm = (warp >> 1) * 64, wn = (warp & 1) * 64;
    const int m0 = blockIdx.x * 128, n0 = blockIdx.y * 128;

    float acc[4][8][4];
    #pragma unroll
    for (int a = 0; a < 4; a++)
        #pragma unroll
        for (int b = 0; b < 8; b++)
            #pragma unroll
            for (int c = 0; c < 4; c++) acc[a][b][c] = 0.f;

    auto issue = [&](int kc, int st) {
        #pragma unroll
        for (int it = 0; it < 4; it++) {
            int v = tid + it * 128;                 // 0..511
            int r = v >> 2, kq = (v & 3) << 3;      // row, k offset (halves)
            cp16(&As[st * 5120 + r * 40 + kq], &g_Ah[(size_t)(m0 + r) * S_DIM + kc * 32 + kq]);
            cp16(&Bs[st * 5120 + r * 40 + kq], &g_Bh[(size_t)(n0 + r) * S_DIM + kc * 32 + kq]);
        }
        cp_commit();
    };

    issue(0, 0); issue(1, 1); issue(2, 2);
    for (int kc = 0; kc < 4; kc++) {
        int left = 3 - kc;
        if (left >= 2)      cp_wait<2>();
        else if (left == 1) cp_wait<1>();
        else                cp_wait<0>();
        __syncthreads();
        const __half* A = &As[(kc % 3) * 5120];
        const __half* B = &Bs[(kc % 3) * 5120];
        #pragma unroll
        for (int kw = 0; kw < 2; kw++) {
            unsigned af[4][4], bf[8][2];
            #pragma unroll
            for (int mt = 0; mt < 4; mt++) {
                int m = wm + mt * 16 + g;
                af[mt][0] = *(const unsigned*)&A[m * 40 + kw * 16 + q * 2];
                af[mt][1] = *(const unsigned*)&A[(m + 8) * 40 + kw * 16 + q * 2];
                af[mt][2] = *(const unsigned*)&A[m * 40 + kw * 16 + q * 2 + 8];
                af[mt][3] = *(const unsigned*)&A[(m + 8) * 40 + kw * 16 + q * 2 + 8];
            }
            #pragma unroll
            for (int nt = 0; nt < 8; nt++) {
                int n = wn + nt * 8 + g;
                bf[nt][0] = *(const unsigned*)&B[n * 40 + kw * 16 + q * 2];
                bf[nt][1] = *(const unsigned*)&B[n * 40 + kw * 16 + q * 2 + 8];
            }
            #pragma unroll
            for (int mt = 0; mt < 4; mt++)
                #pragma unroll
                for (int nt = 0; nt < 8; nt++)
                    mma_f16(acc[mt][nt], af[mt][0], af[mt][1], af[mt][2], af[mt][3],
                            bf[nt][0], bf[nt][1]);
        }
        __syncthreads();
        if (kc + 3 < 4) issue(kc + 3, kc % 3);
    }

    // epilogue: fp16 store
    #pragma unroll
    for (int mt = 0; mt < 4; mt++) {
        int r0 = m0 + wm + mt * 16 + g;
        #pragma unroll
        for (int nt = 0; nt < 8; nt++) {
            int c = n0 + wn + nt * 8 + q * 2;
            __half2 h0, h1;
            h0.x = __float2half(acc[mt][nt][0]); h0.y = __float2half(acc[mt][nt][1]);
            h1.x = __float2half(acc[mt][nt][2]); h1.y = __float2half(acc[mt][nt][3]);
            *(__half2*)&g_S16[(size_t)r0 * M1 + c]       = h0;
            *(__half2*)&g_S16[(size_t)(r0 + 8) * M1 + c] = h1;
        }
    }
}

// ---------------------------------------------------------------------------
// Kernel 3 (fp16): out[i][j][z] = sum_{c,d} S[(i,c)][(j,d)] * woT[z][(c,d)] + bo[z]
//   CTA: one i, 128 j, 128 z. K = 1024 as 32 chunks (one c each, 32 d).
// ---------------------------------------------------------------------------
__global__ __launch_bounds__(128) void k_proj2(const float* __restrict__ bo,
                                               float* __restrict__ out)
{
    extern __shared__ __half smh[];
    __half* As = smh;               // 3 x [128][40]  (rows j, 32 d)
    __half* Bs = smh + 3 * 5120;    // 3 x [128][40]  (rows z, 32 d)

    const int tid  = threadIdx.x;
    const int warp = tid >> 5, lane = tid & 31;
    const int g = lane >> 2, q = lane & 3;
    const int wm = (warp >> 1) * 64, wn = (warp & 1) * 64;
    const int jb = blockIdx.x, i = blockIdx.y;

    float acc[4][8][4];
    #pragma unroll
    for (int a = 0; a < 4; a++)
        #pragma unroll
        for (int b = 0; b < 8; b++)
            #pragma unroll
            for (int c = 0; c < 4; c++) acc[a][b][c] = 0.f;

    auto issue = [&](int c, int st) {
        #pragma unroll
        for (int it = 0; it < 4; it++) {
            int v = tid + it * 128;                 // 0..511
            int r = v >> 2, kq = (v & 3) << 3;
            cp16(&As[st * 5120 + r * 40 + kq],
                 &g_S16[(size_t)(i * 32 + c) * M1 + jb * 4096 + r * 32 + kq]);
            cp16(&Bs[st * 5120 + r * 40 + kq], &g_woT[r * 1024 + c * 32 + kq]);
        }
        cp_commit();
    };

    issue(0, 0); issue(1, 1); issue(2, 2);
    for (int c = 0; c < 32; c++) {
        int left = 31 - c;
        if (left >= 2)      cp_wait<2>();
        else if (left == 1) cp_wait<1>();
        else                cp_wait<0>();
        __syncthreads();
        const __half* A = &As[(c % 3) * 5120];
        const __half* B = &Bs[(c % 3) * 5120];
        #pragma unroll
        for (int kw = 0; kw < 2; kw++) {
            unsigned af[4][4], bf[8][2];
            #pragma unroll
            for (int mt = 0; mt < 4; mt++) {
                int m = wm + mt * 16 + g;
                af[mt][0] = *(const unsigned*)&A[m * 40 + kw * 16 + q * 2];
                af[mt][1] = *(const unsigned*)&A[(m + 8) * 40 + kw * 16 + q * 2];
                af[mt][2] = *(const unsigned*)&A[m * 40 + kw * 16 + q * 2 + 8];
                af[mt][3] = *(const unsigned*)&A[(m + 8) * 40 + kw * 16 + q * 2 + 8];
            }
            #pragma unroll
            for (int nt = 0; nt < 8; nt++) {
                int n = wn + nt * 8 + g;
                bf[nt][0] = *(const unsigned*)&B[n * 40 + kw * 16 + q * 2];
                bf[nt][1] = *(const unsigned*)&B[n * 40 + kw * 16 + q * 2 + 8];
            }
            #pragma unroll
            for (int mt = 0; mt < 4; mt++)
                #pragma unroll
                for (int nt = 0; nt < 8; nt++)
                    mma_f16(acc[mt][nt], af[mt][0], af[mt][1], af[mt][2], af[mt][3],
                            bf[nt][0], bf[nt][1]);
        }
        __syncthreads();
        if (c + 3 < 32) issue(c + 3, c % 3);
    }

    #pragma unroll
    for (int mt = 0; mt < 4; mt++) {
        int j = jb * 128 + wm + mt * 16 + g;
        #pragma unroll
        for (int nt = 0; nt < 8; nt++) {
            int z = wn + nt * 8 + q * 2;
            float b0 = __ldg(&bo[z]), b1 = __ldg(&bo[z + 1]);
            float2 v0, v1;
            v0.x = acc[mt][nt][0] + b0; v0.y = acc[mt][nt][1] + b1;
            v1.x = acc[mt][nt][2] + b0; v1.y = acc[mt][nt][3] + b1;
            *(float2*)&out[(size_t)(i * 256 + j) * 128 + z]     = v0;
            *(float2*)&out[(size_t)(i * 256 + j + 8) * 128 + z] = v1;
        }
    }
}

// ---------------------------------------------------------------------------
extern "C" void kernel_launch(void* const* d_in, const int* in_sizes, int n_in,
                              void* d_out, int out_size)
{
    const float* x   = (const float*)d_in[0];
    const float* lnw = (const float*)d_in[1];
    const float* lnb = (const float*)d_in[2];
    const float* wl  = (const float*)d_in[3];
    const float* bl  = (const float*)d_in[4];
    const float* wr  = (const float*)d_in[5];
    const float* br  = (const float*)d_in[6];
    const float* wo  = (const float*)d_in[7];
    const float* bo  = (const float*)d_in[8];

    const int SMP = (256 * 72 + 2 * 64 * 36 + 512) * 4;        // 94720 B
    const int SMG = 6 * 5120 * 2;                              // 61440 B

    cudaFuncSetAttribute(k_proj,  cudaFuncAttributeMaxDynamicSharedMemorySize, SMP);
    cudaFuncSetAttribute(k_outer, cudaFuncAttributeMaxDynamicSharedMemorySize, SMG);
    cudaFuncSetAttribute(k_proj2, cudaFuncAttributeMaxDynamicSharedMemorySize, SMG);

    k_stats<<<4096, 256>>>(x);
    k_woT<<<128, 256>>>(wo);
    k_proj<<<512, 128, SMP>>>(x, lnw, lnb, wl, bl, wr, br);
    k_outer<<<dim3(64, 64), 128, SMG>>>();
    k_proj2<<<dim3(2, 256), 128, SMG>>>(bo, (float*)d_out);
}